// round 11
// baseline (speedup 1.0000x reference)
#include <cuda_runtime.h>
#include <cuda_bf16.h>

// CovarianceResidualError, single kernel, barrier-free warp-autonomous stream:
//   a_i = graph_emb[i,0];  ACC_j = sum_i e_ij*a_i;  SE_j = sum_i e_ij;  SA = sum_i a_i
//   out = -sum_j |ACC_j - SA*SE_j/N|
//
// 2048 CTAs x 128 threads (occ 8). Each warp independently streams 16 rows
// (a-values in a register lane, __shfl broadcast) -- no __syncthreads and no
// shared memory in the hot loop, so the memory pipeline never drains.
// Deterministic reduction via int64 (2^40 fixed-point) atomics; ticket-elected
// last CTA finalizes and re-zeros state for the next graph replay.

#define NROWS 131072
#define OCOLS 256
#define DCOLS 128
#define NCTA  2048
#define ROWS_CTA 64                        // 16 rows per warp, 4 warps
#define ROWS_W   16

#define SCALE    1099511627776.0f          // 2^40
#define INVSCALE (1.0 / 1099511627776.0)

__device__ unsigned long long g_iacc[OCOLS];
__device__ unsigned long long g_ise [OCOLS];
__device__ unsigned long long g_isa;
__device__ unsigned int g_ct = 0;

__device__ __forceinline__ unsigned long long q40(float v) {
    return (unsigned long long)(long long)llrintf(v * SCALE);
}

__global__ void __launch_bounds__(128, 8)
cov_kernel(const float* __restrict__ ge, const float4* __restrict__ err4,
           float* __restrict__ out)
{
    __shared__ float4 sacc[4][64];
    __shared__ float4 sse [4][64];
    __shared__ float  ssa[4];
    __shared__ unsigned int s_ticket;

    const int tid = threadIdx.x;
    const int w   = tid >> 5;
    const int l   = tid & 31;
    const int r0  = blockIdx.x * ROWS_CTA + w * ROWS_W;   // warp's 16 rows

    // ---- a-values for this warp's 16 rows (one strided load, lanes 0-15) ----
    float av = 0.f;
    if (l < ROWS_W)
        av = ge[(size_t)(r0 + l) * DCOLS];

    // ---- barrier-free stream: 16 rows x 2 float4 per lane ----
    float4 acc1 = make_float4(0.f,0.f,0.f,0.f), acc2 = acc1;
    float4 se1  = acc1, se2 = acc1;

    #pragma unroll
    for (int i = 0; i < ROWS_W; ++i) {
        const float a = __shfl_sync(0xffffffffu, av, i);
        const float4 e1 = __ldcs(&err4[(size_t)(r0 + i) * (OCOLS/4) + l]);
        const float4 e2 = __ldcs(&err4[(size_t)(r0 + i) * (OCOLS/4) + 32 + l]);
        acc1.x = fmaf(e1.x, a, acc1.x); acc1.y = fmaf(e1.y, a, acc1.y);
        acc1.z = fmaf(e1.z, a, acc1.z); acc1.w = fmaf(e1.w, a, acc1.w);
        acc2.x = fmaf(e2.x, a, acc2.x); acc2.y = fmaf(e2.y, a, acc2.y);
        acc2.z = fmaf(e2.z, a, acc2.z); acc2.w = fmaf(e2.w, a, acc2.w);
        se1.x += e1.x; se1.y += e1.y; se1.z += e1.z; se1.w += e1.w;
        se2.x += e2.x; se2.y += e2.y; se2.z += e2.z; se2.w += e2.w;
    }

    // ---- per-warp SA partial (fixed shfl tree over lanes 0-15) ----
    float sa = av;
    #pragma unroll
    for (int off = 8; off > 0; off >>= 1)
        sa += __shfl_down_sync(0xffffffffu, sa, off);
    if (l == 0) ssa[w] = sa;   // lane0 holds sum of lanes 0..15

    // ---- block reduce over the 4 warps (single barrier, post-stream) ----
    sacc[w][l]      = acc1;
    sacc[w][l + 32] = acc2;
    sse [w][l]      = se1;
    sse [w][l + 32] = se2;
    __syncthreads();

    if (tid < 64) {   // col-group g = tid -> columns 4g..4g+3
        float4 A = sacc[0][tid], S = sse[0][tid];
        #pragma unroll
        for (int k = 1; k < 4; ++k) {
            const float4 x = sacc[k][tid], y = sse[k][tid];
            A.x += x.x; A.y += x.y; A.z += x.z; A.w += x.w;
            S.x += y.x; S.y += y.y; S.z += y.z; S.w += y.w;
        }
        atomicAdd(&g_iacc[4*tid+0], q40(A.x));
        atomicAdd(&g_iacc[4*tid+1], q40(A.y));
        atomicAdd(&g_iacc[4*tid+2], q40(A.z));
        atomicAdd(&g_iacc[4*tid+3], q40(A.w));
        atomicAdd(&g_ise [4*tid+0], q40(S.x));
        atomicAdd(&g_ise [4*tid+1], q40(S.y));
        atomicAdd(&g_ise [4*tid+2], q40(S.z));
        atomicAdd(&g_ise [4*tid+3], q40(S.w));
    }
    if (tid == 0)
        atomicAdd(&g_isa, q40(ssa[0] + ssa[1] + ssa[2] + ssa[3]));

    __syncthreads();
    if (tid == 0) {
        __threadfence();
        s_ticket = atomicAdd(&g_ct, 1u);
    }
    __syncthreads();

    // ---- last-finishing CTA finalizes (deterministic fixed-order sum) ----
    if (s_ticket == NCTA - 1) {
        __threadfence();
        const double k = ((double)(long long)g_isa * INVSCALE) / (double)NROWS;

        float v = 0.f;
        #pragma unroll
        for (int p = 0; p < 2; ++p) {
            const int c = tid + p * 128;
            const double A = (double)(long long)g_iacc[c] * INVSCALE;
            const double S = (double)(long long)g_ise [c] * INVSCALE;
            v += (float)fabs(A - k * S);
        }
        // fixed-shape tree over 128 lanes via smem
        ((float*)sacc)[tid] = v;
        __syncthreads();
        #pragma unroll
        for (int st = 64; st > 0; st >>= 1) {
            if (tid < st) ((float*)sacc)[tid] += ((float*)sacc)[tid + st];
            __syncthreads();
        }
        if (tid == 0) out[0] = -((float*)sacc)[0];

        // re-zero for next graph replay
        g_iacc[tid] = 0ull; g_iacc[tid + 128] = 0ull;
        g_ise [tid] = 0ull; g_ise [tid + 128] = 0ull;
        if (tid == 0) { g_isa = 0ull; g_ct = 0u; }
        __threadfence();
    }
}

extern "C" void kernel_launch(void* const* d_in, const int* in_sizes, int n_in,
                              void* d_out, int out_size)
{
    const float* ge  = nullptr;   // graph_emb (N x 128)
    const float* err = nullptr;   // errors    (N x 256)
    for (int i = 0; i < n_in; ++i) {
        if (in_sizes[i] == NROWS * DCOLS) ge  = (const float*)d_in[i];
        else if (in_sizes[i] == NROWS * OCOLS) err = (const float*)d_in[i];
    }

    cov_kernel<<<NCTA, 128>>>(ge, (const float4*)err, (float*)d_out);
}

// round 12
// speedup vs baseline: 3.0754x; 3.0754x over previous
#include <cuda_runtime.h>
#include <cuda_bf16.h>
#include <cstdint>

// CovarianceResidualError, single kernel, cp.async.bulk (TMA-class) stream:
//   a_i = graph_emb[i,0];  ACC_j = sum_i e_ij*a_i;  SE_j = sum_i e_ij;  SA = sum_i a_i
//   out = -sum_j |ACC_j - SA*SE_j/N|
//
// Register-MLP LDG streaming pinned at ~5TB/s (DRAM 64%). Each CTA's 256 rows
// of errors are 256KB contiguous -> 1D cp.async.bulk into a 2-stage 16KB smem
// ring (mbarrier complete_tx), decoupling bytes-in-flight from registers.
// Deterministic reduction: per-chunk order is fixed per thread; cross-CTA
// combine via int64 (2^40) atomics (exact integer adds commute); ticket-
// elected last CTA finalizes and re-zeros state for the next graph replay.

#define NROWS 131072
#define OCOLS 256
#define DCOLS 128
#define NB 512
#define ROWS_PER_BLK (NROWS / NB)          // 256
#define CROWS 16                           // rows per bulk chunk
#define NCHUNKS (ROWS_PER_BLK / CROWS)     // 16
#define NSTG 2
#define CBYTES (CROWS * OCOLS * 4)         // 16384

#define SCALE    1099511627776.0f          // 2^40
#define INVSCALE (1.0 / 1099511627776.0)

__device__ unsigned long long g_iacc[OCOLS];
__device__ unsigned long long g_ise [OCOLS];
__device__ unsigned long long g_isa;
__device__ unsigned int g_ct = 0;

__device__ __forceinline__ unsigned long long q40(float v) {
    return (unsigned long long)(long long)llrintf(v * SCALE);
}

__device__ __forceinline__ void mbar_init(uint32_t mbar, uint32_t count) {
    asm volatile("mbarrier.init.shared.b64 [%0], %1;" :: "r"(mbar), "r"(count) : "memory");
}
__device__ __forceinline__ void mbar_expect_tx(uint32_t mbar, uint32_t bytes) {
    asm volatile("mbarrier.arrive.expect_tx.shared.b64 _, [%0], %1;"
                 :: "r"(mbar), "r"(bytes) : "memory");
}
__device__ __forceinline__ void bulk_g2s(uint32_t dst, const void* src,
                                         uint32_t bytes, uint32_t mbar) {
    asm volatile(
        "cp.async.bulk.shared::cluster.global.mbarrier::complete_tx::bytes "
        "[%0], [%1], %2, [%3];"
        :: "r"(dst), "l"(src), "r"(bytes), "r"(mbar) : "memory");
}
__device__ __forceinline__ void mbar_wait(uint32_t mbar, uint32_t phase) {
    asm volatile(
        "{\n\t"
        ".reg .pred P;\n\t"
        "WAIT_%=:\n\t"
        "mbarrier.try_wait.parity.acquire.cta.shared::cta.b64 P, [%0], %1, 0x989680;\n\t"
        "@P bra.uni DONE_%=;\n\t"
        "bra.uni WAIT_%=;\n\t"
        "DONE_%=:\n\t"
        "}"
        :: "r"(mbar), "r"(phase) : "memory");
}

__global__ void __launch_bounds__(256, 4)
cov_kernel(const float* __restrict__ ge, const float* __restrict__ err,
           float* __restrict__ out)
{
    __shared__ __align__(16) float4 buf[NSTG][CROWS][OCOLS / 4];   // 32 KB
    __shared__ float red[4 * OCOLS];                               // 4 KB
    __shared__ float ssa[4];
    __shared__ unsigned long long mbar_arr[NSTG];
    __shared__ unsigned int s_ticket;

    const int tid = threadIdx.x;
    const int tx  = tid & 63;      // column group: columns 4*tx .. 4*tx+3
    const int ty  = tid >> 6;      // row phase 0..3 (fixed per warp)
    const int w   = tid >> 5;
    const int l   = tid & 31;
    const int bid = blockIdx.x;
    const int r0  = bid * ROWS_PER_BLK;

    const uint32_t mb0 = (uint32_t)__cvta_generic_to_shared(&mbar_arr[0]);
    if (tid == 0) {
        mbar_init(mb0, 1);
        mbar_init(mb0 + 8, 1);
    }
    asm volatile("fence.proxy.async.shared::cta;" ::: "memory");
    __syncthreads();

    // Prologue: fill both stages
    const char* src_base = (const char*)err + (size_t)r0 * OCOLS * 4;
    if (tid == 0) {
        #pragma unroll
        for (int s = 0; s < NSTG; ++s) {
            const uint32_t dst = (uint32_t)__cvta_generic_to_shared(&buf[s][0][0]);
            mbar_expect_tx(mb0 + 8 * s, CBYTES);
            bulk_g2s(dst, src_base + (size_t)s * CBYTES, CBYTES, mb0 + 8 * s);
        }
    }

    float4 acc = make_float4(0.f, 0.f, 0.f, 0.f);
    float4 se  = make_float4(0.f, 0.f, 0.f, 0.f);
    float  sa  = 0.f;

    for (int c = 0; c < NCHUNKS; ++c) {
        const int s   = c & 1;
        const int phi = (c >> 1) & 1;
        const int cr0 = r0 + c * CROWS;

        // a-values for this chunk: lanes 0..3 of every warp load rows ty+4k
        float av = 0.f;
        if (l < 4)
            av = ge[(size_t)(cr0 + ty + 4 * l) * DCOLS];

        mbar_wait(mb0 + 8 * s, phi);

        #pragma unroll
        for (int k = 0; k < 4; ++k) {
            const float  a = __shfl_sync(0xffffffffu, av, k);
            const float4 e = buf[s][ty + 4 * k][tx];
            acc.x = fmaf(e.x, a, acc.x); acc.y = fmaf(e.y, a, acc.y);
            acc.z = fmaf(e.z, a, acc.z); acc.w = fmaf(e.w, a, acc.w);
            se.x += e.x; se.y += e.y; se.z += e.z; se.w += e.w;
        }
        sa += av;   // lanes>=4 hold 0

        __syncthreads();   // stage s fully consumed by all threads
        if (tid == 0 && c + NSTG < NCHUNKS) {
            const uint32_t dst = (uint32_t)__cvta_generic_to_shared(&buf[s][0][0]);
            mbar_expect_tx(mb0 + 8 * s, CBYTES);
            bulk_g2s(dst, src_base + (size_t)(c + NSTG) * CBYTES, CBYTES, mb0 + 8 * s);
        }
    }

    // ---- SA: even warps (w&1==0) own rows; lanes 0..3 hold partials ----
    sa += __shfl_down_sync(0xffffffffu, sa, 2);
    sa += __shfl_down_sync(0xffffffffu, sa, 1);
    if ((w & 1) == 0 && l == 0) ssa[w >> 1] = sa;

    // ---- reduce the 4 row phases (deterministic, via shared) ----
    __syncthreads();
    red[ty * OCOLS + 4 * tx + 0] = acc.x;
    red[ty * OCOLS + 4 * tx + 1] = acc.y;
    red[ty * OCOLS + 4 * tx + 2] = acc.z;
    red[ty * OCOLS + 4 * tx + 3] = acc.w;
    __syncthreads();
    const float accTot =
        red[tid] + red[OCOLS + tid] + red[2 * OCOLS + tid] + red[3 * OCOLS + tid];
    __syncthreads();
    red[ty * OCOLS + 4 * tx + 0] = se.x;
    red[ty * OCOLS + 4 * tx + 1] = se.y;
    red[ty * OCOLS + 4 * tx + 2] = se.z;
    red[ty * OCOLS + 4 * tx + 3] = se.w;
    __syncthreads();
    const float seTot =
        red[tid] + red[OCOLS + tid] + red[2 * OCOLS + tid] + red[3 * OCOLS + tid];

    // Deterministic global accumulation (order-independent integer adds)
    atomicAdd(&g_iacc[tid], q40(accTot));
    atomicAdd(&g_ise [tid], q40(seTot));
    if (tid == 0)
        atomicAdd(&g_isa, q40(ssa[0] + ssa[1] + ssa[2] + ssa[3]));

    __syncthreads();
    if (tid == 0) {
        __threadfence();
        s_ticket = atomicAdd(&g_ct, 1u);
    }
    __syncthreads();

    // ---- last-finishing CTA finalizes ----
    if (s_ticket == NB - 1) {
        __threadfence();
        const double A = (double)(long long)g_iacc[tid] * INVSCALE;
        const double S = (double)(long long)g_ise [tid] * INVSCALE;
        const double k = ((double)(long long)g_isa * INVSCALE) / (double)NROWS;

        red[tid] = (float)fabs(A - k * S);
        __syncthreads();
        #pragma unroll
        for (int st = 128; st > 0; st >>= 1) {
            if (tid < st) red[tid] += red[tid + st];
            __syncthreads();
        }
        if (tid == 0) out[0] = -red[0];

        // re-zero for the next graph replay
        g_iacc[tid] = 0ull;
        g_ise [tid] = 0ull;
        if (tid == 0) { g_isa = 0ull; g_ct = 0u; }
        __threadfence();
    }
}

extern "C" void kernel_launch(void* const* d_in, const int* in_sizes, int n_in,
                              void* d_out, int out_size)
{
    const float* ge  = nullptr;   // graph_emb (N x 128)
    const float* err = nullptr;   // errors    (N x 256)
    for (int i = 0; i < n_in; ++i) {
        if (in_sizes[i] == NROWS * DCOLS) ge  = (const float*)d_in[i];
        else if (in_sizes[i] == NROWS * OCOLS) err = (const float*)d_in[i];
    }

    cov_kernel<<<NB, 256>>>(ge, err, (float*)d_out);
}

// round 13
// speedup vs baseline: 3.3023x; 1.0738x over previous
#include <cuda_runtime.h>
#include <cuda_bf16.h>

// CovarianceResidualError, single kernel, GLOBAL GRID-STRIDE interleave:
//   a_i = graph_emb[i,0];  ACC_j = sum_i e_ij*a_i;  SE_j = sum_i e_ij;  SA = sum_i a_i
//   out = -sum_j |ACC_j - SA*SE_j/N|
//
// Private-region streaming (LDG and TMA alike) pinned at ~5TB/s: outstanding
// reads scattered over the full 134MB thrash HBM row buffers. Grid-stride
// interleave makes the whole chip sweep one contiguous ~2MB row-window per
// step (131072 threads = exactly one float4 per row-window element), fixed
// column-group per thread. Deterministic int64 (2^40) atomic combine
// (integer adds commute); ticket-elected last CTA finalizes and re-zeros.

#define NROWS 131072
#define OCOLS 256
#define DCOLS 128
#define NB 512
#define NSTEPS 64                          // 131072*64 float4 / 131072 threads

#define SCALE    1099511627776.0f          // 2^40
#define INVSCALE (1.0 / 1099511627776.0)

__device__ unsigned long long g_iacc[OCOLS];
__device__ unsigned long long g_ise [OCOLS];
__device__ unsigned long long g_isa;
__device__ unsigned int g_ct = 0;

__device__ __forceinline__ unsigned long long q40(float v) {
    return (unsigned long long)(long long)llrintf(v * SCALE);
}

__global__ void __launch_bounds__(256, 4)
cov_kernel(const float* __restrict__ ge, const float4* __restrict__ err4,
           float* __restrict__ out)
{
    __shared__ float red[4 * OCOLS];
    __shared__ float ssa[4];
    __shared__ unsigned int s_ticket;

    const int tid = threadIdx.x;
    const int w   = tid >> 5;          // warp 0..7
    const int l   = tid & 31;          // lane
    const int bid = blockIdx.x;
    const size_t gth = (size_t)bid * 256 + tid;   // global thread id

    // Each warp covers half a row per step; its row index:
    const int rowbase = bid * 4 + (w >> 1);

    float4 acc = make_float4(0.f, 0.f, 0.f, 0.f);
    float4 se  = make_float4(0.f, 0.f, 0.f, 0.f);
    float  sa  = 0.f;

    #pragma unroll 8
    for (int k = 0; k < NSTEPS; ++k) {
        const int row = rowbase + k * 2048;
        float av = 0.f;
        if (l == 0)
            av = __ldcs(&ge[(size_t)row * DCOLS]);
        const float a = __shfl_sync(0xffffffffu, av, 0);

        const float4 e = __ldcs(&err4[gth + (size_t)k * (NROWS * (OCOLS / 4) / 64)]);
        // stride per step = 131072 float4 (whole grid) -> contiguous 2MB window
        acc.x = fmaf(e.x, a, acc.x); acc.y = fmaf(e.y, a, acc.y);
        acc.z = fmaf(e.z, a, acc.z); acc.w = fmaf(e.w, a, acc.w);
        se.x += e.x; se.y += e.y; se.z += e.z; se.w += e.w;

        if ((w & 1) == 0) sa += a;     // each row counted once (even warps)
    }

    // ---- SA partials: lane 0 of even warps holds this warp's 64-row sum ----
    if ((w & 1) == 0 && l == 0) ssa[w >> 1] = sa;

    // ---- reduce 4 row-phases per column group (deterministic, via shared) ----
    // Thread's column group = tid & 63 (fixed all kernel); phase = tid >> 6.
    const int tx = tid & 63;
    const int ty = tid >> 6;
    __syncthreads();
    red[ty * OCOLS + 4 * tx + 0] = acc.x;
    red[ty * OCOLS + 4 * tx + 1] = acc.y;
    red[ty * OCOLS + 4 * tx + 2] = acc.z;
    red[ty * OCOLS + 4 * tx + 3] = acc.w;
    __syncthreads();
    const float accTot =
        red[tid] + red[OCOLS + tid] + red[2 * OCOLS + tid] + red[3 * OCOLS + tid];
    __syncthreads();
    red[ty * OCOLS + 4 * tx + 0] = se.x;
    red[ty * OCOLS + 4 * tx + 1] = se.y;
    red[ty * OCOLS + 4 * tx + 2] = se.z;
    red[ty * OCOLS + 4 * tx + 3] = se.w;
    __syncthreads();
    const float seTot =
        red[tid] + red[OCOLS + tid] + red[2 * OCOLS + tid] + red[3 * OCOLS + tid];

    // Deterministic global accumulation (order-independent integer adds)
    atomicAdd(&g_iacc[tid], q40(accTot));
    atomicAdd(&g_ise [tid], q40(seTot));
    if (tid == 0)
        atomicAdd(&g_isa, q40(ssa[0] + ssa[1] + ssa[2] + ssa[3]));

    __syncthreads();
    if (tid == 0) {
        __threadfence();
        s_ticket = atomicAdd(&g_ct, 1u);
    }
    __syncthreads();

    // ---- last-finishing CTA finalizes ----
    if (s_ticket == NB - 1) {
        __threadfence();
        const double A = (double)(long long)g_iacc[tid] * INVSCALE;
        const double S = (double)(long long)g_ise [tid] * INVSCALE;
        const double kk = ((double)(long long)g_isa * INVSCALE) / (double)NROWS;

        red[tid] = (float)fabs(A - kk * S);
        __syncthreads();
        #pragma unroll
        for (int st = 128; st > 0; st >>= 1) {
            if (tid < st) red[tid] += red[tid + st];
            __syncthreads();
        }
        if (tid == 0) out[0] = -red[0];

        // re-zero for the next graph replay
        g_iacc[tid] = 0ull;
        g_ise [tid] = 0ull;
        if (tid == 0) { g_isa = 0ull; g_ct = 0u; }
        __threadfence();
    }
}

extern "C" void kernel_launch(void* const* d_in, const int* in_sizes, int n_in,
                              void* d_out, int out_size)
{
    const float* ge  = nullptr;   // graph_emb (N x 128)
    const float* err = nullptr;   // errors    (N x 256)
    for (int i = 0; i < n_in; ++i) {
        if (in_sizes[i] == NROWS * DCOLS) ge  = (const float*)d_in[i];
        else if (in_sizes[i] == NROWS * OCOLS) err = (const float*)d_in[i];
    }

    cov_kernel<<<NB, 256>>>(ge, (const float4*)err, (float*)d_out);
}